// round 15
// baseline (speedup 1.0000x reference)
#include <cuda_runtime.h>

// Problem constants
#define B_   16
#define NQ_  2048
#define NK_  2048
#define D_   128
#define BM   64      // q rows per CTA
#define BN   64      // keys per k-tile
#define QP   132     // smem pitch (floats) for Q/K/V tiles
#define PP   80      // smem pitch for P tile
#define NSEG 4
#define SEGLEN (NK_ / NSEG)
#define NTHR 512     // 16 warps -> 4 warps/SMSP

// Per-batch masked-V partial suffix sums (scratch; __device__ global per allocation rules)
__device__ float g_mvs[NSEG * B_ * D_];

// ---------------- packed f32x2 helpers (Blackwell FFMA2 path) ----------------
__device__ __forceinline__ unsigned long long pk(float a, float b) {
    unsigned long long r;
    asm("mov.b64 %0, {%1, %2};" : "=l"(r) : "f"(a), "f"(b));
    return r;
}
__device__ __forceinline__ void upk(unsigned long long v, float& a, float& b) {
    asm("mov.b64 {%0, %1}, %2;" : "=f"(a), "=f"(b) : "l"(v));
}
__device__ __forceinline__ void fma2(unsigned long long& d, unsigned long long a, unsigned long long b) {
    asm("fma.rn.f32x2 %0, %1, %2, %0;" : "+l"(d) : "l"(a), "l"(b));
}
__device__ __forceinline__ void mul2(unsigned long long& d, unsigned long long a) {
    asm("mul.rn.f32x2 %0, %0, %1;" : "+l"(d) : "l"(a));
}

// ---------------------------------------------------------------------------
// valid_lens dtype-robust load (reference says int64; JAX x64-off emits int32).
// First 16 int32 words are in-bounds for both layouts; all-odd-words-zero
// identifies little-endian int64.
// ---------------------------------------------------------------------------
__device__ __forceinline__ int load_L(const void* vlp, int b) {
    const int* w = (const int*)vlp;
    bool i64 = true;
#pragma unroll
    for (int i = 1; i < 16; i += 2) i64 &= (w[i] == 0);
    int L = i64 ? w[2 * b] : w[b];
    return min(max(L, 0), NK_);
}

// ---------------------------------------------------------------------------
// Kernel A: masked V suffix sums.
// g_mvs[s][b][d] = sum_{k in [s*512,(s+1)*512) ∩ [L,2048)} V[b,k,d]
// ---------------------------------------------------------------------------
__global__ void mvs_kernel(const float* __restrict__ V, const void* __restrict__ vl) {
    int b = blockIdx.x, s = blockIdx.y, d = threadIdx.x;
    int L = load_L(vl, b);
    int k1 = (s + 1) * SEGLEN;
    int k  = max(L, s * SEGLEN);
    const float* vb = V + (size_t)b * NK_ * D_;
    float s0 = 0.f, s1 = 0.f, s2 = 0.f, s3 = 0.f;
    for (; k + 4 <= k1; k += 4) {
        s0 += vb[(k + 0) * D_ + d];
        s1 += vb[(k + 1) * D_ + d];
        s2 += vb[(k + 2) * D_ + d];
        s3 += vb[(k + 3) * D_ + d];
    }
    for (; k < k1; k++) s0 += vb[k * D_ + d];
    g_mvs[(s * B_ + b) * D_ + d] = (s0 + s1) + (s2 + s3);
}

// ---------------------------------------------------------------------------
// Kernel B: flash attention over k < L, online softmax seeded with the masked
// mass (score == 1e-8 exactly => m0=1e-8, l0=Nk-L, acc0=sum masked V).
//
// 512 threads as 32x16 (ty = tid>>4, tx = tid&15).
//   S rows owned:  ty + 32*i,       i in 0..1
//   S cols owned:  tx + 16*j,       j in 0..3
//   O cols owned:  2*tx + 32*jj+{0,1}, jj in 0..3  (f32x2 pairs)
// ---------------------------------------------------------------------------
__global__ __launch_bounds__(NTHR, 1)
void attn_kernel(const float* __restrict__ Q, const float* __restrict__ K,
                 const float* __restrict__ V, const void* __restrict__ vl,
                 float* __restrict__ O) {
    extern __shared__ float sm[];
    float* sQ = sm;                    // BM x QP
    float* sK = sQ + BM * QP;          // BN x QP
    float* sV = sK + BN * QP;          // BN x QP
    float* sP = sV + BN * QP;          // BM x PP

    const int b   = blockIdx.y;
    const int q0  = blockIdx.x * BM;
    const int tid = threadIdx.x;
    const int ty  = tid >> 4;          // 0..31
    const int tx  = tid & 15;          // 0..15

    const int L = load_L(vl, b);

    const float* Qb = Q + ((size_t)b * NQ_ + q0) * D_;
    const float* Kb = K + (size_t)b * NK_ * D_;
    const float* Vb = V + (size_t)b * NK_ * D_;

    // ---- load Q tile (64 x 128 fp32) ----
#pragma unroll
    for (int it = 0; it < (BM * D_ / 4) / NTHR; it++) {
        int idx = tid + it * NTHR;
        int row = idx >> 5;
        int c4  = idx & 31;
        float4 v = *(const float4*)(Qb + row * D_ + c4 * 4);
        *(float4*)(sQ + row * QP + c4 * 4) = v;
    }

    // ---- init accumulators with masked contribution (packed pairs) ----
    unsigned long long acc2[2][4];
#pragma unroll
    for (int jj = 0; jj < 4; jj++) {
        float a0 = 0.f, a1 = 0.f;
#pragma unroll
        for (int sg = 0; sg < NSEG; sg++) {
            float2 m = *(const float2*)(g_mvs + (sg * B_ + b) * D_ + 2 * tx + 32 * jj);
            a0 += m.x; a1 += m.y;
        }
        unsigned long long v = pk(a0, a1);
        acc2[0][jj] = v; acc2[1][jj] = v;
    }
    float mrow[2], lrow[2];
    const float linit = (float)(NK_ - L);
#pragma unroll
    for (int i = 0; i < 2; i++) { mrow[i] = 1e-8f; lrow[i] = linit; }

    const int nTiles = (L + BN - 1) / BN;
    const float scale = 0.08838834764831845f;  // 1/sqrt(128)

    for (int kt = 0; kt < nTiles; kt++) {
        // ---- load K,V tiles ----
        const float* Kt = Kb + (size_t)kt * BN * D_;
        const float* Vt = Vb + (size_t)kt * BN * D_;
#pragma unroll
        for (int it = 0; it < (BN * D_ / 4) / NTHR; it++) {
            int idx = tid + it * NTHR;
            int row = idx >> 5;
            int c4  = idx & 31;
            float4 kv = *(const float4*)(Kt + row * D_ + c4 * 4);
            float4 vv = *(const float4*)(Vt + row * D_ + c4 * 4);
            *(float4*)(sK + row * QP + c4 * 4) = kv;
            *(float4*)(sV + row * QP + c4 * 4) = vv;
        }
        __syncthreads();

        // ---- GEMM1: S = Q K^T  (2x4 per thread, f32x2 along k) ----
        unsigned long long s2[2][4];
#pragma unroll
        for (int i = 0; i < 2; i++)
#pragma unroll
            for (int j = 0; j < 4; j++) s2[i][j] = 0ull;

#pragma unroll 4
        for (int kk = 0; kk < D_; kk += 4) {
            double2 qd[2], kd[4];
#pragma unroll
            for (int i = 0; i < 2; i++) qd[i] = *(const double2*)(sQ + (ty + 32 * i) * QP + kk);
#pragma unroll
            for (int j = 0; j < 4; j++) kd[j] = *(const double2*)(sK + (tx + 16 * j) * QP + kk);
#pragma unroll
            for (int i = 0; i < 2; i++)
#pragma unroll
                for (int j = 0; j < 4; j++) {
                    fma2(s2[i][j], __double_as_longlong(qd[i].x), __double_as_longlong(kd[j].x));
                    fma2(s2[i][j], __double_as_longlong(qd[i].y), __double_as_longlong(kd[j].y));
                }
        }

        // ---- masking + online softmax ----
        const int kbase = kt * BN;
        const bool fullvalid = (kbase + BN) <= L;
#pragma unroll
        for (int i = 0; i < 2; i++) {
            float sv[4];
            float tm = -1e30f;
#pragma unroll
            for (int j = 0; j < 4; j++) {
                float a, c; upk(s2[i][j], a, c);
                float s = (a + c) * scale;
                if (!fullvalid && (kbase + tx + 16 * j) >= L) s = -1e30f;  // excluded (seeded)
                sv[j] = s;
                tm = fmaxf(tm, s);
            }
#pragma unroll
            for (int off = 8; off; off >>= 1)
                tm = fmaxf(tm, __shfl_xor_sync(0xffffffffu, tm, off));
            float mnew = fmaxf(mrow[i], tm);
            float r = __expf(mrow[i] - mnew);
            float ps = 0.f;
            float p[4];
#pragma unroll
            for (int j = 0; j < 4; j++) {
                p[j] = __expf(sv[j] - mnew);
                ps += p[j];
            }
#pragma unroll
            for (int off = 8; off; off >>= 1)
                ps += __shfl_xor_sync(0xffffffffu, ps, off);
            lrow[i] = lrow[i] * r + ps;
            mrow[i] = mnew;
            unsigned long long rp = pk(r, r);
#pragma unroll
            for (int jj = 0; jj < 4; jj++) mul2(acc2[i][jj], rp);
#pragma unroll
            for (int j = 0; j < 4; j++)
                sP[(ty + 32 * i) * PP + tx + 16 * j] = p[j];
        }
        __syncthreads();

        // ---- GEMM2: acc += P V  (2 rows x 4 col-pairs per thread, f32x2) ----
#pragma unroll 2
        for (int kk4 = 0; kk4 < BN; kk4 += 4) {
            float4 pv4[2];
#pragma unroll
            for (int i = 0; i < 2; i++)
                pv4[i] = *(const float4*)(sP + (ty + 32 * i) * PP + kk4);
            float pr[2][4];
#pragma unroll
            for (int i = 0; i < 2; i++) {
                pr[i][0] = pv4[i].x; pr[i][1] = pv4[i].y;
                pr[i][2] = pv4[i].z; pr[i][3] = pv4[i].w;
            }
#pragma unroll
            for (int t = 0; t < 4; t++) {
                const float* vrow = sV + (kk4 + t) * QP + 2 * tx;
                unsigned long long vv[4];
#pragma unroll
                for (int jj = 0; jj < 4; jj++)
                    vv[jj] = *(const unsigned long long*)(vrow + 32 * jj);
                unsigned long long pp0 = pk(pr[0][t], pr[0][t]);
                unsigned long long pp1 = pk(pr[1][t], pr[1][t]);
#pragma unroll
                for (int jj = 0; jj < 4; jj++) {
                    fma2(acc2[0][jj], pp0, vv[jj]);
                    fma2(acc2[1][jj], pp1, vv[jj]);
                }
            }
        }
        __syncthreads();  // protect sK/sV/sP before next tile's loads
    }

    // ---- epilogue: normalize and store (float2 per jj, coalesced) ----
    float* Ob = O + ((size_t)b * NQ_ + q0) * D_;
#pragma unroll
    for (int i = 0; i < 2; i++) {
        float inv = 1.0f / lrow[i];   // lrow >= 1 always
        unsigned long long ip = pk(inv, inv);
#pragma unroll
        for (int jj = 0; jj < 4; jj++) {
            mul2(acc2[i][jj], ip);
            *(unsigned long long*)(Ob + (ty + 32 * i) * D_ + 2 * tx + 32 * jj) = acc2[i][jj];
        }
    }
}

// ---------------------------------------------------------------------------
extern "C" void kernel_launch(void* const* d_in, const int* in_sizes, int n_in,
                              void* d_out, int out_size) {
    const float* Q = (const float*)d_in[0];
    const float* K = (const float*)d_in[1];
    const float* V = (const float*)d_in[2];
    const void*  vl = d_in[3];
    float* O = (float*)d_out;

    mvs_kernel<<<dim3(B_, NSEG), D_>>>(V, vl);

    size_t smem = (size_t)(3 * BM * QP + BM * PP) * sizeof(float);
    cudaFuncSetAttribute(attn_kernel, cudaFuncAttributeMaxDynamicSharedMemorySize, (int)smem);
    attn_kernel<<<dim3(NQ_ / BM, B_), NTHR, smem>>>(Q, K, V, vl, O);
}

// round 16
// speedup vs baseline: 1.4278x; 1.4278x over previous
#include <cuda_runtime.h>

// Problem constants
#define B_   16
#define NQ_  2048
#define NK_  2048
#define D_   128
#define BM   64      // q rows per CTA
#define BN   64      // keys per k-tile
#define QP   132     // smem pitch (floats): 132%32=4 -> K-frag float4 loads only 2-way conflicted
#define PP   80      // smem pitch for P tile
#define NSEG 4
#define SEGLEN (NK_ / NSEG)
#define NTHR 256     // 8 warps, big per-thread tiles (R14 shape)

// Per-batch masked-V partial suffix sums (scratch; __device__ global per allocation rules)
__device__ float g_mvs[NSEG * B_ * D_];

// ---------------- packed f32x2 helpers (Blackwell FFMA2 path) ----------------
__device__ __forceinline__ unsigned long long pk(float a, float b) {
    unsigned long long r;
    asm("mov.b64 %0, {%1, %2};" : "=l"(r) : "f"(a), "f"(b));
    return r;
}
__device__ __forceinline__ void upk(unsigned long long v, float& a, float& b) {
    asm("mov.b64 {%0, %1}, %2;" : "=f"(a), "=f"(b) : "l"(v));
}
__device__ __forceinline__ void fma2(unsigned long long& d, unsigned long long a, unsigned long long b) {
    asm("fma.rn.f32x2 %0, %1, %2, %0;" : "+l"(d) : "l"(a), "l"(b));
}
__device__ __forceinline__ void mul2(unsigned long long& d, unsigned long long a) {
    asm("mul.rn.f32x2 %0, %0, %1;" : "+l"(d) : "l"(a));
}

// ---------------------------------------------------------------------------
// valid_lens dtype-robust load (reference says int64; JAX x64-off emits int32).
// First 16 int32 words are in-bounds for both layouts; all-odd-words-zero
// identifies little-endian int64.
// ---------------------------------------------------------------------------
__device__ __forceinline__ int load_L(const void* vlp, int b) {
    const int* w = (const int*)vlp;
    bool i64 = true;
#pragma unroll
    for (int i = 1; i < 16; i += 2) i64 &= (w[i] == 0);
    int L = i64 ? w[2 * b] : w[b];
    return min(max(L, 0), NK_);
}

// ---------------------------------------------------------------------------
// Kernel A: masked V suffix sums.
// g_mvs[s][b][d] = sum_{k in [s*512,(s+1)*512) ∩ [L,2048)} V[b,k,d]
// ---------------------------------------------------------------------------
__global__ void mvs_kernel(const float* __restrict__ V, const void* __restrict__ vl) {
    int b = blockIdx.x, s = blockIdx.y, d = threadIdx.x;
    int L = load_L(vl, b);
    int k1 = (s + 1) * SEGLEN;
    int k  = max(L, s * SEGLEN);
    const float* vb = V + (size_t)b * NK_ * D_;
    float s0 = 0.f, s1 = 0.f, s2 = 0.f, s3 = 0.f;
    for (; k + 4 <= k1; k += 4) {
        s0 += vb[(k + 0) * D_ + d];
        s1 += vb[(k + 1) * D_ + d];
        s2 += vb[(k + 2) * D_ + d];
        s3 += vb[(k + 3) * D_ + d];
    }
    for (; k < k1; k++) s0 += vb[k * D_ + d];
    g_mvs[(s * B_ + b) * D_ + d] = (s0 + s1) + (s2 + s3);
}

// ---------------------------------------------------------------------------
// Kernel B: flash attention over k < L; online softmax seeded with the masked
// mass (masked score == 1e-8 exactly => m0=1e-8, l0=Nk-L, acc0=sum masked V).
//
// 256 threads as 16x16 (ty, tx).
//   S rows owned:  ty + 16*i, i in 0..3
//   S cols owned:  tx + 16*j, j in 0..3      (GEMM1/softmax, k-dim packed f32x2)
//   O cols owned:  2*tx + 32*jj + {0,1}, jj in 0..3   (GEMM2, col-pair f32x2)
// Q is pre-scaled by 1/sqrt(d) at smem load.
// ---------------------------------------------------------------------------
__global__ __launch_bounds__(NTHR, 1)
void attn_kernel(const float* __restrict__ Q, const float* __restrict__ K,
                 const float* __restrict__ V, const void* __restrict__ vl,
                 float* __restrict__ O) {
    extern __shared__ float sm[];
    float* sQ = sm;                    // BM x QP  (pre-scaled)
    float* sK = sQ + BM * QP;          // BN x QP
    float* sV = sK + BN * QP;          // BN x QP
    float* sP = sV + BN * QP;          // BM x PP

    const int b   = blockIdx.y;
    const int q0  = blockIdx.x * BM;
    const int tid = threadIdx.x;
    const int ty  = tid >> 4;
    const int tx  = tid & 15;

    const int L = load_L(vl, b);
    const float scale = 0.08838834764831845f;  // 1/sqrt(128)

    const float* Qb = Q + ((size_t)b * NQ_ + q0) * D_;
    const float* Kb = K + (size_t)b * NK_ * D_;
    const float* Vb = V + (size_t)b * NK_ * D_;

    // ---- load Q tile (64 x 128 fp32), pre-scaled ----
#pragma unroll
    for (int it = 0; it < (BM * D_ / 4) / NTHR; it++) {
        int idx = tid + it * NTHR;
        int row = idx >> 5;
        int c4  = idx & 31;
        float4 v = *(const float4*)(Qb + row * D_ + c4 * 4);
        v.x *= scale; v.y *= scale; v.z *= scale; v.w *= scale;
        *(float4*)(sQ + row * QP + c4 * 4) = v;
    }

    // ---- init accumulators with masked contribution (col pairs) ----
    unsigned long long acc2[4][4];
#pragma unroll
    for (int jj = 0; jj < 4; jj++) {
        float a0 = 0.f, a1 = 0.f;
#pragma unroll
        for (int sg = 0; sg < NSEG; sg++) {
            float2 m = *(const float2*)(g_mvs + (sg * B_ + b) * D_ + 2 * tx + 32 * jj);
            a0 += m.x; a1 += m.y;
        }
        unsigned long long v = pk(a0, a1);
#pragma unroll
        for (int i = 0; i < 4; i++) acc2[i][jj] = v;
    }
    float mrow[4], lrow[4];
    const float linit = (float)(NK_ - L);
#pragma unroll
    for (int i = 0; i < 4; i++) { mrow[i] = 1e-8f; lrow[i] = linit; }

    const int nTiles = (L + BN - 1) / BN;

    for (int kt = 0; kt < nTiles; kt++) {
        // ---- load K,V tiles ----
        const float* Kt = Kb + (size_t)kt * BN * D_;
        const float* Vt = Vb + (size_t)kt * BN * D_;
#pragma unroll
        for (int it = 0; it < (BN * D_ / 4) / NTHR; it++) {
            int idx = tid + it * NTHR;
            int row = idx >> 5;
            int c4  = idx & 31;
            float4 kv = *(const float4*)(Kt + row * D_ + c4 * 4);
            float4 vv = *(const float4*)(Vt + row * D_ + c4 * 4);
            *(float4*)(sK + row * QP + c4 * 4) = kv;
            *(float4*)(sV + row * QP + c4 * 4) = vv;
        }
        __syncthreads();

        // ---- GEMM1: S = Q K^T (4x4 per thread; f32x2 packed along k) ----
        unsigned long long s2[4][4];
#pragma unroll
        for (int i = 0; i < 4; i++)
#pragma unroll
            for (int j = 0; j < 4; j++) s2[i][j] = 0ull;

#pragma unroll 4
        for (int kk = 0; kk < D_; kk += 4) {
            double2 qd[4], kd[4];
#pragma unroll
            for (int i = 0; i < 4; i++) qd[i] = *(const double2*)(sQ + (ty + 16 * i) * QP + kk);
#pragma unroll
            for (int j = 0; j < 4; j++) kd[j] = *(const double2*)(sK + (tx + 16 * j) * QP + kk);
#pragma unroll
            for (int i = 0; i < 4; i++)
#pragma unroll
                for (int j = 0; j < 4; j++) {
                    fma2(s2[i][j], __double_as_longlong(qd[i].x), __double_as_longlong(kd[j].x));
                    fma2(s2[i][j], __double_as_longlong(qd[i].y), __double_as_longlong(kd[j].y));
                }
        }

        // ---- masking + online softmax (scores already scaled via Q) ----
        const int kbase = kt * BN;
        const bool fullvalid = (kbase + BN) <= L;
#pragma unroll
        for (int i = 0; i < 4; i++) {
            float sv[4];
            float tm = -1e30f;
#pragma unroll
            for (int j = 0; j < 4; j++) {
                float a, c; upk(s2[i][j], a, c);
                float s = a + c;
                if (!fullvalid && (kbase + tx + 16 * j) >= L) s = -1e30f;  // excluded (seeded)
                sv[j] = s;
                tm = fmaxf(tm, s);
            }
#pragma unroll
            for (int off = 8; off; off >>= 1)
                tm = fmaxf(tm, __shfl_xor_sync(0xffffffffu, tm, off));
            float mnew = fmaxf(mrow[i], tm);
            float r = __expf(mrow[i] - mnew);
            float ps = 0.f;
            float p[4];
#pragma unroll
            for (int j = 0; j < 4; j++) {
                p[j] = __expf(sv[j] - mnew);
                ps += p[j];
            }
#pragma unroll
            for (int off = 8; off; off >>= 1)
                ps += __shfl_xor_sync(0xffffffffu, ps, off);
            lrow[i] = lrow[i] * r + ps;
            mrow[i] = mnew;
            unsigned long long rp = pk(r, r);
#pragma unroll
            for (int jj = 0; jj < 4; jj++) mul2(acc2[i][jj], rp);
#pragma unroll
            for (int j = 0; j < 4; j++)
                sP[(ty + 16 * i) * PP + tx + 16 * j] = p[j];
        }
        __syncthreads();

        // ---- GEMM2: acc += P V (4 rows x 4 col-pairs; f32x2) ----
#pragma unroll 2
        for (int kk4 = 0; kk4 < BN; kk4 += 4) {
            float4 pv4[4];
#pragma unroll
            for (int i = 0; i < 4; i++)
                pv4[i] = *(const float4*)(sP + (ty + 16 * i) * PP + kk4);
#pragma unroll
            for (int t = 0; t < 4; t++) {
                const float* vrow = sV + (kk4 + t) * QP + 2 * tx;
                unsigned long long vv[4];
#pragma unroll
                for (int jj = 0; jj < 4; jj++)
                    vv[jj] = *(const unsigned long long*)(vrow + 32 * jj);
                float pt0 = (t == 0) ? pv4[0].x : (t == 1) ? pv4[0].y : (t == 2) ? pv4[0].z : pv4[0].w;
                float pt1 = (t == 0) ? pv4[1].x : (t == 1) ? pv4[1].y : (t == 2) ? pv4[1].z : pv4[1].w;
                float pt2 = (t == 0) ? pv4[2].x : (t == 1) ? pv4[2].y : (t == 2) ? pv4[2].z : pv4[2].w;
                float pt3 = (t == 0) ? pv4[3].x : (t == 1) ? pv4[3].y : (t == 2) ? pv4[3].z : pv4[3].w;
                unsigned long long pp[4] = { pk(pt0, pt0), pk(pt1, pt1), pk(pt2, pt2), pk(pt3, pt3) };
#pragma unroll
                for (int i = 0; i < 4; i++)
#pragma unroll
                    for (int jj = 0; jj < 4; jj++)
                        fma2(acc2[i][jj], pp[i], vv[jj]);
            }
        }
        __syncthreads();  // protect sK/sV/sP before next tile's loads
    }

    // ---- epilogue: normalize and store (8B stores, conflict-free pattern) ----
    float* Ob = O + ((size_t)b * NQ_ + q0) * D_;
#pragma unroll
    for (int i = 0; i < 4; i++) {
        float inv = 1.0f / lrow[i];   // lrow >= 1 always
        unsigned long long ip = pk(inv, inv);
#pragma unroll
        for (int jj = 0; jj < 4; jj++) {
            mul2(acc2[i][jj], ip);
            *(unsigned long long*)(Ob + (ty + 16 * i) * D_ + 2 * tx + 32 * jj) = acc2[i][jj];
        }
    }
}

// ---------------------------------------------------------------------------
extern "C" void kernel_launch(void* const* d_in, const int* in_sizes, int n_in,
                              void* d_out, int out_size) {
    const float* Q = (const float*)d_in[0];
    const float* K = (const float*)d_in[1];
    const float* V = (const float*)d_in[2];
    const void*  vl = d_in[3];
    float* O = (float*)d_out;

    mvs_kernel<<<dim3(B_, NSEG), D_>>>(V, vl);

    size_t smem = (size_t)(3 * BM * QP + BM * PP) * sizeof(float);
    cudaFuncSetAttribute(attn_kernel, cudaFuncAttributeMaxDynamicSharedMemorySize, (int)smem);
    attn_kernel<<<dim3(NQ_ / BM, B_), NTHR, smem>>>(Q, K, V, vl, O);
}